// round 13
// baseline (speedup 1.0000x reference)
#include <cuda_runtime.h>
#include <cuda_bf16.h>
#include <cstdint>

// ---------------------------------------------------------------------------
// Shapes (fixed)
// ---------------------------------------------------------------------------
#define NTOK 4096            // B*T
#define HDIM 4096
#define SDIM 1024
#define FDIM 9984
#define KTAY 6144            // S*G

// ---------------------------------------------------------------------------
// Scratch (__device__ globals; allocation-free)
// ---------------------------------------------------------------------------
__device__ __nv_bfloat16 g_Xhi [NTOK * HDIM], g_Xlo [NTOK * HDIM];
__device__ __nv_bfloat16 g_upwh[SDIM * HDIM], g_upwl[SDIM * HDIM];
__device__ __nv_bfloat16 g_gwh [SDIM * HDIM], g_gwl [SDIM * HDIM];
__device__ __nv_bfloat16 g_laoh[HDIM * SDIM], g_laol[HDIM * SDIM];
__device__ __nv_bfloat16 g_fwh [HDIM * KTAY], g_fwl [HDIM * KTAY];
__device__ __nv_bfloat16 g_fgwh[(size_t)FDIM * HDIM], g_fgwl[(size_t)FDIM * HDIM];
__device__ __nv_bfloat16 g_fuwh[(size_t)FDIM * HDIM], g_fuwl[(size_t)FDIM * HDIM];
__device__ __nv_bfloat16 g_fdwh[(size_t)HDIM * FDIM], g_fdwl[(size_t)HDIM * FDIM];
__device__ float         g_AU  [NTOK * SDIM], g_GP  [NTOK * SDIM];
__device__ __nv_bfloat16 g_AUh [NTOK * SDIM], g_AUl [NTOK * SDIM];
__device__ __nv_bfloat16 g_TMPh[NTOK * KTAY], g_TMPl[NTOK * KTAY];
__device__ float         g_BG  [(size_t)NTOK * FDIM];
__device__ __nv_bfloat16 g_Ph  [(size_t)NTOK * FDIM], g_Pl[(size_t)NTOK * FDIM];

// ---------------------------------------------------------------------------
// Baseline-PTX helpers
// ---------------------------------------------------------------------------
__device__ __forceinline__ uint32_t smem_u32(const void* p) {
    uint32_t a;
    asm("{ .reg .u64 t; cvta.to.shared.u64 t, %1; cvt.u32.u64 %0, t; }" : "=r"(a) : "l"(p));
    return a;
}
__device__ __forceinline__ void cpasync16(uint32_t dst, const void* src) {
    asm volatile("cp.async.cg.shared.global [%0], [%1], 16;" :: "r"(dst), "l"(src) : "memory");
}
__device__ __forceinline__ void cp_commit() {
    asm volatile("cp.async.commit_group;" ::: "memory");
}
template <int N>
__device__ __forceinline__ void cp_wait() {
    asm volatile("cp.async.wait_group %0;" :: "n"(N) : "memory");
}
__device__ __forceinline__ void ldm4(uint32_t* r, uint32_t a) {
    asm volatile("ldmatrix.sync.aligned.m8n8.x4.shared.b16 {%0,%1,%2,%3}, [%4];"
                 : "=r"(r[0]), "=r"(r[1]), "=r"(r[2]), "=r"(r[3]) : "r"(a));
}
__device__ __forceinline__ void mma16816(float* d, const uint32_t* a, uint32_t b0, uint32_t b1) {
    asm volatile("mma.sync.aligned.m16n8k16.row.col.f32.bf16.bf16.f32 "
                 "{%0,%1,%2,%3}, {%4,%5,%6,%7}, {%8,%9}, {%0,%1,%2,%3};"
                 : "+f"(d[0]), "+f"(d[1]), "+f"(d[2]), "+f"(d[3])
                 : "r"(a[0]), "r"(a[1]), "r"(a[2]), "r"(a[3]), "r"(b0), "r"(b1));
}
__device__ __forceinline__ uint32_t cvt_bf16x2(float lo_el, float hi_el) {
    uint32_t r;
    asm("cvt.rn.bf16x2.f32 %0, %1, %2;" : "=r"(r) : "f"(hi_el), "f"(lo_el));
    return r;
}
__device__ __forceinline__ float bf_lo_f(uint32_t p) { return __uint_as_float(p << 16); }
__device__ __forceinline__ float bf_hi_f(uint32_t p) { return __uint_as_float(p & 0xffff0000u); }
__device__ __forceinline__ float silu_mul(float g, float u) {
    return g / (1.f + expf(-g)) * u;
}

// ---------------------------------------------------------------------------
// Split-bf16 tensor-core GEMM (3-pass: Ah*Bh + Ah*Bl + Al*Bh, fp32 accum).
// (2-pass measured 1.74e-3 end-to-end in R10 -> over threshold; keep 3-pass.)
// CTA tile 128x128, BK=32, 256 thr (8 warps 2x4), warp tile 64x32.
// 3-stage cp.async ring, one __syncthreads per k-block, 2 CTAs/SM.
// SMEM: unpadded 64B rows + XOR swizzle (chunk' = chunk ^ ((row>>1)&3)).
// Panel-swizzled CTA map (PANEL_W in bx, by-fastest inside).
// R13: multi-segment K (up to 3 operand pairs accumulate into one tile),
//      epilogue modes: 0 = store fp32 C
//                      1 = DUAL proj: store fp32 C/C2; path A also emits
//                          bf16 hi/lo (Oh/Ol)
//                      2 = silu: p = silu(G_tile) * acc -> Oh/Ol only
// Requires M%128==0, each K%32==0 with K/32 >= 2.
// ---------------------------------------------------------------------------
#define BK        32
#define ROWB      64
#define SA_HI     0
#define SA_LO     (128 * ROWB)
#define SB_HI     (2 * 128 * ROWB)
#define SB_LO     (3 * 128 * ROWB)
#define STAGE_B   (4 * 128 * ROWB)         // 32768
#define NSTAGE    3
#define SMEM_TOTAL (NSTAGE * STAGE_B)      // 98304 (x2 CTAs = 192KB)
#define PANEL_W   8

struct GemmArgs {
    const __nv_bfloat16 *Ah0, *Al0, *Bh0, *Bl0;
    const __nv_bfloat16 *Ah1, *Al1, *Bh1, *Bl1;
    const __nv_bfloat16 *Ah2, *Al2, *Bh2, *Bl2;
    int K0, K1, K2;
    float* C; int M;
    const __nv_bfloat16 *B2h, *B2l;   // DUAL second B
    float* C2; int msplit;            // DUAL second C, bx split point
    const float* G;                   // EPI=2 gate tile source
    __nv_bfloat16 *Oh, *Ol;           // EPI=1/2 bf16 hi/lo outputs
};

template <int EPI, int NSEG, int DUAL>
__global__ void __launch_bounds__(256, 2)
tc_gemm(GemmArgs a)
{
    extern __shared__ char smem[];
    const uint32_t sb = smem_u32(smem);
    const int t    = threadIdx.x;
    const int lane = t & 31;
    const int w    = t >> 5;
    const int wm   = w >> 2;
    const int wn   = w & 3;

    // ---- panel-swizzled CTA mapping ----
    int bx, by;
    {
        const int gx = gridDim.x, gy = gridDim.y;
        int bid = blockIdx.y * gx + blockIdx.x;
        int fp  = gx / PANEL_W;
        int rem = gx - fp * PANEL_W;
        int cf  = fp * PANEL_W * gy;
        if (bid < cf) {
            int p = bid / (PANEL_W * gy);
            int r = bid - p * (PANEL_W * gy);
            bx = p * PANEL_W + (r % PANEL_W);
            by = r / PANEL_W;
        } else {
            int r = bid - cf;
            bx = fp * PANEL_W + (r % rem);
            by = r / rem;
        }
    }

    bool alt = false;
    if (DUAL && bx >= a.msplit) { alt = true; bx -= a.msplit; }

    // cooperative store mapping (smem side is segment-invariant)
    int r0 = t >> 2, c0 = t & 3;
    int r1 = r0 + 64;
    int cs = c0 ^ ((r0 >> 1) & 3);
    uint32_t so0 = (uint32_t)r0 * ROWB + cs * 16;
    uint32_t so1 = (uint32_t)r1 * ROWB + cs * 16;

    // ldmatrix per-lane components
    const int la_r  = lane & 15;
    const int la_sw = (la_r >> 1) & 3;
    const int la_c  = lane >> 4;
    const int lb_r  = (lane & 7) + ((lane >> 4) << 3);
    const int lb_sw = (lb_r >> 1) & 3;
    const int lb_c  = (lane >> 3) & 1;

    float acc[4][4][4];
#pragma unroll
    for (int mi = 0; mi < 4; mi++)
#pragma unroll
        for (int ni = 0; ni < 4; ni++)
#pragma unroll
            for (int q = 0; q < 4; q++) acc[mi][ni][q] = 0.f;

#pragma unroll
    for (int sg = 0; sg < NSEG; sg++) {
        const __nv_bfloat16* sAh = (sg == 0) ? a.Ah0 : (sg == 1) ? a.Ah1 : a.Ah2;
        const __nv_bfloat16* sAl = (sg == 0) ? a.Al0 : (sg == 1) ? a.Al1 : a.Al2;
        const __nv_bfloat16* sBh = (sg == 0) ? a.Bh0 : (sg == 1) ? a.Bh1 : a.Bh2;
        const __nv_bfloat16* sBl = (sg == 0) ? a.Bl0 : (sg == 1) ? a.Bl1 : a.Bl2;
        const int K = (sg == 0) ? a.K0 : (sg == 1) ? a.K1 : a.K2;
        if (DUAL && sg == 0 && alt) { sBh = a.B2h; sBl = a.B2l; }

        const size_t rs = (size_t)K * 2;
        const char* Ah = (const char*)sAh + (size_t)by * 128 * rs;
        const char* Al = (const char*)sAl + (size_t)by * 128 * rs;
        const char* Bh = (const char*)sBh + (size_t)bx * 128 * rs;
        const char* Bl = (const char*)sBl + (size_t)bx * 128 * rs;
        const int KB = K / BK;
        size_t go0 = (size_t)r0 * rs + c0 * 16;
        size_t go1 = (size_t)r1 * rs + c0 * 16;

#define LOAD_STAGE(kb, buf)                                                  \
    do {                                                                     \
        uint32_t st = sb + (uint32_t)(buf) * STAGE_B;                        \
        size_t   kofs = (size_t)(kb) * 64;                                   \
        cpasync16(st + SA_HI + so0, Ah + go0 + kofs);                        \
        cpasync16(st + SA_HI + so1, Ah + go1 + kofs);                        \
        cpasync16(st + SA_LO + so0, Al + go0 + kofs);                        \
        cpasync16(st + SA_LO + so1, Al + go1 + kofs);                        \
        cpasync16(st + SB_HI + so0, Bh + go0 + kofs);                        \
        cpasync16(st + SB_HI + so1, Bh + go1 + kofs);                        \
        cpasync16(st + SB_LO + so0, Bl + go0 + kofs);                        \
        cpasync16(st + SB_LO + so1, Bl + go1 + kofs);                        \
        cp_commit();                                                         \
    } while (0)

        LOAD_STAGE(0, 0);
        LOAD_STAGE(1, 1);

        int buf = 0, nbuf = 2;
        for (int kb = 0; kb < KB; kb++) {
            if (kb + 1 < KB) cp_wait<1>(); else cp_wait<0>();
            __syncthreads();
            if (kb + 2 < KB) LOAD_STAGE(kb + 2, nbuf);

            const uint32_t st = sb + (uint32_t)buf * STAGE_B;
#pragma unroll
            for (int kk = 0; kk < 2; kk++) {
                const uint32_t ca = (uint32_t)((kk * 2 + la_c) ^ la_sw) * 16;
                const uint32_t cb = (uint32_t)((kk * 2 + lb_c) ^ lb_sw) * 16;
                uint32_t bhf[2][4], blf[2][4];
#pragma unroll
                for (int pr = 0; pr < 2; pr++) {
                    uint32_t base = (uint32_t)(wn * 32 + pr * 16 + lb_r) * ROWB + cb;
                    ldm4(bhf[pr], st + SB_HI + base);
                    ldm4(blf[pr], st + SB_LO + base);
                }
#pragma unroll
                for (int mi = 0; mi < 4; mi++) {
                    uint32_t ah[4], al[4];
                    uint32_t base = (uint32_t)(wm * 64 + mi * 16 + la_r) * ROWB + ca;
                    ldm4(ah, st + SA_HI + base);
                    ldm4(al, st + SA_LO + base);
#pragma unroll
                    for (int ni = 0; ni < 4; ni++) {
                        const int pr = ni >> 1, hf = (ni & 1) * 2;
                        mma16816(acc[mi][ni], ah, bhf[pr][hf], bhf[pr][hf + 1]);
                        mma16816(acc[mi][ni], ah, blf[pr][hf], blf[pr][hf + 1]);
                        mma16816(acc[mi][ni], al, bhf[pr][hf], bhf[pr][hf + 1]);
                    }
                }
            }
            buf  = (buf  == 2) ? 0 : buf + 1;
            nbuf = (nbuf == 2) ? 0 : nbuf + 1;
        }
        // smem hazard fence before next segment's stage-0 loads
        if (sg + 1 < NSEG) __syncthreads();
#undef LOAD_STAGE
    }

    // ---- epilogue ----
    const int M = a.M;
    const int erow = by * 128 + wm * 64 + (lane >> 2);
    const int ecol = bx * 128 + wn * 32 + (lane & 3) * 2;
    float* CS = (DUAL && alt) ? a.C2 : a.C;

#pragma unroll
    for (int mi = 0; mi < 4; mi++) {
#pragma unroll
        for (int ni = 0; ni < 4; ni++) {
            const int row = erow + mi * 16;
            const int col = ecol + ni * 8;
            float q0 = acc[mi][ni][0], q1 = acc[mi][ni][1];
            float q2 = acc[mi][ni][2], q3 = acc[mi][ni][3];
            if (EPI == 2) {
                // silu: read gate tile, combine, emit bf16 hi/lo only
                float2 g0 = *(const float2*)(a.G + (size_t)row * M + col);
                float2 g1 = *(const float2*)(a.G + (size_t)(row + 8) * M + col);
                float p0 = silu_mul(g0.x, q0), p1 = silu_mul(g0.y, q1);
                float p2 = silu_mul(g1.x, q2), p3 = silu_mul(g1.y, q3);
                uint32_t h0 = cvt_bf16x2(p0, p1);
                uint32_t h1 = cvt_bf16x2(p2, p3);
                *(uint32_t*)(a.Oh + (size_t)row * M + col)       = h0;
                *(uint32_t*)(a.Oh + (size_t)(row + 8) * M + col) = h1;
                uint32_t l0 = cvt_bf16x2(p0 - bf_lo_f(h0), p1 - bf_hi_f(h0));
                uint32_t l1 = cvt_bf16x2(p2 - bf_lo_f(h1), p3 - bf_hi_f(h1));
                *(uint32_t*)(a.Ol + (size_t)row * M + col)       = l0;
                *(uint32_t*)(a.Ol + (size_t)(row + 8) * M + col) = l1;
            } else {
                *(float2*)(CS + (size_t)row * M + col)       = make_float2(q0, q1);
                *(float2*)(CS + (size_t)(row + 8) * M + col) = make_float2(q2, q3);
                if (EPI == 1 && !alt) {
                    uint32_t h0 = cvt_bf16x2(q0, q1);
                    uint32_t h1 = cvt_bf16x2(q2, q3);
                    *(uint32_t*)(a.Oh + (size_t)row * M + col)       = h0;
                    *(uint32_t*)(a.Oh + (size_t)(row + 8) * M + col) = h1;
                    uint32_t l0 = cvt_bf16x2(q0 - bf_lo_f(h0), q1 - bf_hi_f(h0));
                    uint32_t l1 = cvt_bf16x2(q2 - bf_lo_f(h1), q3 - bf_hi_f(h1));
                    *(uint32_t*)(a.Ol + (size_t)row * M + col)       = l0;
                    *(uint32_t*)(a.Ol + (size_t)(row + 8) * M + col) = l1;
                }
            }
        }
    }
}

// ---------------------------------------------------------------------------
// fp32 -> (hi, lo) bf16 split. Unit = 2 float4 (8 elems); 4 units/thread.
// ---------------------------------------------------------------------------
__global__ void split8(const float4* __restrict__ src,
                       uint4* __restrict__ hi, uint4* __restrict__ lo, int n8)
{
    int u0 = blockIdx.x * (blockDim.x * 4) + threadIdx.x;
    float4 a[4], b[4];
    bool   ok[4];
#pragma unroll
    for (int j = 0; j < 4; j++) {
        int u = u0 + j * 256;
        ok[j] = (u < n8);
        if (ok[j]) { a[j] = src[2 * (size_t)u]; b[j] = src[2 * (size_t)u + 1]; }
    }
#pragma unroll
    for (int j = 0; j < 4; j++) {
        if (!ok[j]) continue;
        int u = u0 + j * 256;
        uint32_t h0 = cvt_bf16x2(a[j].x, a[j].y);
        uint32_t h1 = cvt_bf16x2(a[j].z, a[j].w);
        uint32_t h2 = cvt_bf16x2(b[j].x, b[j].y);
        uint32_t h3 = cvt_bf16x2(b[j].z, b[j].w);
        hi[u] = make_uint4(h0, h1, h2, h3);
        uint32_t l0 = cvt_bf16x2(a[j].x - bf_lo_f(h0), a[j].y - bf_hi_f(h0));
        uint32_t l1 = cvt_bf16x2(a[j].z - bf_lo_f(h1), a[j].w - bf_hi_f(h1));
        uint32_t l2 = cvt_bf16x2(b[j].x - bf_lo_f(h2), b[j].y - bf_hi_f(h2));
        uint32_t l3 = cvt_bf16x2(b[j].z - bf_lo_f(h3), b[j].w - bf_hi_f(h3));
        lo[u] = make_uint4(l0, l1, l2, l3);
    }
}

// ---------------------------------------------------------------------------
// Taylor coefficients -> split bf16 TMP[t, s*6+g]
// ---------------------------------------------------------------------------
__global__ void taylor_kernel(const float* __restrict__ AU, const float* __restrict__ GP,
                              const float* __restrict__ lp, const float* __restrict__ df,
                              __nv_bfloat16* __restrict__ TMPh, __nv_bfloat16* __restrict__ TMPl)
{
    int idx = blockIdx.x * blockDim.x + threadIdx.x;    // t*1024 + s
    if (idx >= NTOK * SDIM) return;
    int s = idx & (SDIM - 1);

    float au    = AU[idx];
    float delta = GP[idx] - lp[s];
    float neg   = (delta > 0.f) ? 1.f : -1.f;
    float ad    = fabsf(delta);
    float ld    = logf(ad);
    float keep  = (ad <= 2.5f) ? 1.f : 0.f;

    float v[6];
#pragma unroll
    for (int g = 0; g < 6; g++) {
        int   m = g + 1;
        float dterm = expf(ld * (float)m - df[g]);
        if (m & 1) dterm *= neg;
        float x = dterm * au;
        if (m > 4) x *= keep;
        v[g] = x;
    }
    uint32_t h[3], l[3];
#pragma unroll
    for (int q = 0; q < 3; q++) {
        h[q] = cvt_bf16x2(v[2 * q], v[2 * q + 1]);
        l[q] = cvt_bf16x2(v[2 * q] - bf_lo_f(h[q]), v[2 * q + 1] - bf_hi_f(h[q]));
    }
    uint32_t* ph = (uint32_t*)(TMPh + (size_t)idx * 6);
    uint32_t* pl = (uint32_t*)(TMPl + (size_t)idx * 6);
    ph[0] = h[0]; ph[1] = h[1]; ph[2] = h[2];
    pl[0] = l[0]; pl[1] = l[1]; pl[2] = l[2];
}

// ---------------------------------------------------------------------------
// kernel_launch
// ---------------------------------------------------------------------------
static inline void run_split(const float* src, __nv_bfloat16* hi, __nv_bfloat16* lo, size_t n) {
    int n8 = (int)(n >> 3);
    split8<<<(n8 + 1023) / 1024, 256>>>((const float4*)src, (uint4*)hi, (uint4*)lo, n8);
}

extern "C" void kernel_launch(void* const* d_in, const int* in_sizes, int n_in,
                              void* d_out, int out_size)
{
    const float* X   = (const float*)d_in[0];   // [4096,4096]
    const float* upw = (const float*)d_in[1];   // [1024,4096]
    const float* gw  = (const float*)d_in[2];   // [1024,4096]
    const float* lp  = (const float*)d_in[3];   // [1024]
    const float* lao = (const float*)d_in[4];   // [4096,1024]
    const float* fw  = (const float*)d_in[5];   // [4096,6144]
    const float* df  = (const float*)d_in[6];   // [6]
    const float* fgw = (const float*)d_in[7];   // [9984,4096]
    const float* fuw = (const float*)d_in[8];   // [9984,4096]
    const float* fdw = (const float*)d_in[9];   // [4096,9984]
    float* out       = (float*)d_out;           // [4096,4096]

    cudaFuncSetAttribute(tc_gemm<0, 1, 0>, cudaFuncAttributeMaxDynamicSharedMemorySize, SMEM_TOTAL);
    cudaFuncSetAttribute(tc_gemm<0, 3, 0>, cudaFuncAttributeMaxDynamicSharedMemorySize, SMEM_TOTAL);
    cudaFuncSetAttribute(tc_gemm<1, 1, 1>, cudaFuncAttributeMaxDynamicSharedMemorySize, SMEM_TOTAL);
    cudaFuncSetAttribute(tc_gemm<2, 1, 0>, cudaFuncAttributeMaxDynamicSharedMemorySize, SMEM_TOTAL);

#define SYM(p, s) cudaGetSymbolAddress((void**)&p, s)
    __nv_bfloat16 *Xh, *Xl, *upwh, *upwl, *gwh, *gwl, *laoh, *laol, *fwh, *fwl;
    __nv_bfloat16 *fgwh, *fgwl, *fuwh, *fuwl, *fdwh, *fdwl;
    __nv_bfloat16 *AUh, *AUl, *TMPh, *TMPl, *Ph, *Pl;
    float *AU, *GP, *BG;
    SYM(Xh, g_Xhi);   SYM(Xl, g_Xlo);
    SYM(upwh, g_upwh); SYM(upwl, g_upwl);
    SYM(gwh, g_gwh);   SYM(gwl, g_gwl);
    SYM(laoh, g_laoh); SYM(laol, g_laol);
    SYM(fwh, g_fwh);   SYM(fwl, g_fwl);
    SYM(fgwh, g_fgwh); SYM(fgwl, g_fgwl);
    SYM(fuwh, g_fuwh); SYM(fuwl, g_fuwl);
    SYM(fdwh, g_fdwh); SYM(fdwl, g_fdwl);
    SYM(AU, g_AU);     SYM(GP, g_GP);
    SYM(AUh, g_AUh);   SYM(AUl, g_AUl);
    SYM(TMPh, g_TMPh); SYM(TMPl, g_TMPl);
    SYM(BG, g_BG);
    SYM(Ph, g_Ph);     SYM(Pl, g_Pl);
#undef SYM

    // --- fp32 -> hi/lo bf16 conversions (inputs only) ---
    run_split(X,   Xh,   Xl,   (size_t)NTOK * HDIM);
    run_split(upw, upwh, upwl, (size_t)SDIM * HDIM);
    run_split(gw,  gwh,  gwl,  (size_t)SDIM * HDIM);
    run_split(lao, laoh, laol, (size_t)HDIM * SDIM);
    run_split(fw,  fwh,  fwl,  (size_t)HDIM * KTAY);
    run_split(fgw, fgwh, fgwl, (size_t)FDIM * HDIM);
    run_split(fuw, fuwh, fuwl, (size_t)FDIM * HDIM);
    run_split(fdw, fdwh, fdwl, (size_t)HDIM * FDIM);

    GemmArgs a{};

    // 1+2 merged (DUAL, EPI=1): AU = X@up_w^T (+ AUh/AUl emitted in epilogue),
    // GP = X@gate_w^T. grid (16, 32).
    a = GemmArgs{};
    a.Ah0 = Xh; a.Al0 = Xl; a.Bh0 = upwh; a.Bl0 = upwl; a.K0 = HDIM;
    a.C = AU; a.M = SDIM;
    a.B2h = gwh; a.B2l = gwl; a.C2 = GP; a.msplit = SDIM / 128;
    a.Oh = AUh; a.Ol = AUl;
    tc_gemm<1, 1, 1><<<dim3(2 * SDIM / 128, NTOK / 128), 256, SMEM_TOTAL>>>(a);

    // 3: Taylor coefficients -> TMP hi/lo
    taylor_kernel<<<(NTOK * SDIM) / 256, 256>>>(AU, GP, lp, df, TMPh, TMPl);

    // 6: FFN gate -> BG (fp32). grid (78, 32).
    a = GemmArgs{};
    a.Ah0 = Xh; a.Al0 = Xl; a.Bh0 = fgwh; a.Bl0 = fgwl; a.K0 = HDIM;
    a.C = BG; a.M = FDIM;
    tc_gemm<0, 1, 0><<<dim3(FDIM / 128, NTOK / 128), 256, SMEM_TOTAL>>>(a);

    // 7: FFN up with fused silu epilogue: P = silu(BG) * (X@fuw^T) -> Ph/Pl.
    a = GemmArgs{};
    a.Ah0 = Xh; a.Al0 = Xl; a.Bh0 = fuwh; a.Bl0 = fuwl; a.K0 = HDIM;
    a.M = FDIM; a.G = BG; a.Oh = Ph; a.Ol = Pl;
    tc_gemm<2, 1, 0><<<dim3(FDIM / 128, NTOK / 128), 256, SMEM_TOTAL>>>(a);

    // 4+5+9 merged (3-segment K): out = AU@lao^T + TMP@fw^T + P@fdw^T.
    // grid (32, 32), K = 1024 + 6144 + 9984.
    a = GemmArgs{};
    a.Ah0 = AUh;  a.Al0 = AUl;  a.Bh0 = laoh; a.Bl0 = laol; a.K0 = SDIM;
    a.Ah1 = TMPh; a.Al1 = TMPl; a.Bh1 = fwh;  a.Bl1 = fwl;  a.K1 = KTAY;
    a.Ah2 = Ph;   a.Al2 = Pl;   a.Bh2 = fdwh; a.Bl2 = fdwl; a.K2 = FDIM;
    a.C = out; a.M = HDIM;
    tc_gemm<0, 3, 0><<<dim3(HDIM / 128, NTOK / 128), 256, SMEM_TOTAL>>>(a);
}

// round 14
// speedup vs baseline: 1.0044x; 1.0044x over previous
#include <cuda_runtime.h>
#include <cuda_bf16.h>
#include <cstdint>

// ---------------------------------------------------------------------------
// Shapes (fixed)
// ---------------------------------------------------------------------------
#define NTOK 4096            // B*T
#define HDIM 4096
#define SDIM 1024
#define FDIM 9984
#define KTAY 6144            // S*G

// ---------------------------------------------------------------------------
// Scratch (__device__ globals; allocation-free)
// ---------------------------------------------------------------------------
__device__ __nv_bfloat16 g_Xhi [NTOK * HDIM], g_Xlo [NTOK * HDIM];
__device__ __nv_bfloat16 g_upwh[SDIM * HDIM], g_upwl[SDIM * HDIM];
__device__ __nv_bfloat16 g_gwh [SDIM * HDIM], g_gwl [SDIM * HDIM];
__device__ __nv_bfloat16 g_laoh[HDIM * SDIM], g_laol[HDIM * SDIM];
__device__ __nv_bfloat16 g_fwh [HDIM * KTAY], g_fwl [HDIM * KTAY];
__device__ __nv_bfloat16 g_fgwh[(size_t)FDIM * HDIM], g_fgwl[(size_t)FDIM * HDIM];
__device__ __nv_bfloat16 g_fuwh[(size_t)FDIM * HDIM], g_fuwl[(size_t)FDIM * HDIM];
__device__ __nv_bfloat16 g_fdwh[(size_t)HDIM * FDIM], g_fdwl[(size_t)HDIM * FDIM];
__device__ float         g_AU  [NTOK * SDIM], g_GP  [NTOK * SDIM];
__device__ __nv_bfloat16 g_AUh [NTOK * SDIM], g_AUl [NTOK * SDIM];
__device__ __nv_bfloat16 g_TMPh[NTOK * KTAY], g_TMPl[NTOK * KTAY];
__device__ float         g_BG  [(size_t)NTOK * FDIM];
__device__ __nv_bfloat16 g_Ph  [(size_t)NTOK * FDIM], g_Pl[(size_t)NTOK * FDIM];

// ---------------------------------------------------------------------------
// Baseline-PTX helpers
// ---------------------------------------------------------------------------
__device__ __forceinline__ uint32_t smem_u32(const void* p) {
    uint32_t a;
    asm("{ .reg .u64 t; cvta.to.shared.u64 t, %1; cvt.u32.u64 %0, t; }" : "=r"(a) : "l"(p));
    return a;
}
__device__ __forceinline__ void cpasync16(uint32_t dst, const void* src) {
    asm volatile("cp.async.cg.shared.global [%0], [%1], 16;" :: "r"(dst), "l"(src) : "memory");
}
__device__ __forceinline__ void cp_commit() {
    asm volatile("cp.async.commit_group;" ::: "memory");
}
template <int N>
__device__ __forceinline__ void cp_wait() {
    asm volatile("cp.async.wait_group %0;" :: "n"(N) : "memory");
}
__device__ __forceinline__ void ldm4(uint32_t* r, uint32_t a) {
    asm volatile("ldmatrix.sync.aligned.m8n8.x4.shared.b16 {%0,%1,%2,%3}, [%4];"
                 : "=r"(r[0]), "=r"(r[1]), "=r"(r[2]), "=r"(r[3]) : "r"(a));
}
__device__ __forceinline__ void mma16816(float* d, const uint32_t* a, uint32_t b0, uint32_t b1) {
    asm volatile("mma.sync.aligned.m16n8k16.row.col.f32.bf16.bf16.f32 "
                 "{%0,%1,%2,%3}, {%4,%5,%6,%7}, {%8,%9}, {%0,%1,%2,%3};"
                 : "+f"(d[0]), "+f"(d[1]), "+f"(d[2]), "+f"(d[3])
                 : "r"(a[0]), "r"(a[1]), "r"(a[2]), "r"(a[3]), "r"(b0), "r"(b1));
}
__device__ __forceinline__ uint32_t cvt_bf16x2(float lo_el, float hi_el) {
    uint32_t r;
    asm("cvt.rn.bf16x2.f32 %0, %1, %2;" : "=r"(r) : "f"(hi_el), "f"(lo_el));
    return r;
}
__device__ __forceinline__ float bf_lo_f(uint32_t p) { return __uint_as_float(p << 16); }
__device__ __forceinline__ float bf_hi_f(uint32_t p) { return __uint_as_float(p & 0xffff0000u); }
__device__ __forceinline__ float silu_mul(float g, float u) {
    return g / (1.f + expf(-g)) * u;
}

// ---------------------------------------------------------------------------
// Split-bf16 tensor-core GEMM (3-pass: Ah*Bh + Ah*Bl + Al*Bh, fp32 accum).
// (2-pass measured 1.74e-3 end-to-end in R10 -> over threshold; keep 3-pass.
//  3-segment K-merge measured +280us in R13 -> reverted; single-segment only.)
// CTA tile 128x128, BK=32, 256 thr (8 warps 2x4), warp tile 64x32.
// 3-stage cp.async ring, one __syncthreads per k-block, 2 CTAs/SM.
// SMEM: unpadded 64B rows + XOR swizzle (chunk' = chunk ^ ((row>>1)&3)).
// Panel-swizzled CTA map (PANEL_W in bx, by-fastest inside).
// Epilogue modes: EPI=0 -> fp32 C (BETA: += existing C)
//                 EPI=1 -> DUAL proj: fp32 C/C2; path A also emits Oh/Ol
//                 EPI=2 -> silu: p = silu(G_tile) * acc -> Oh/Ol only
// Requires M%128==0, K%32==0.
// ---------------------------------------------------------------------------
#define BK        32
#define ROWB      64
#define SA_HI     0
#define SA_LO     (128 * ROWB)
#define SB_HI     (2 * 128 * ROWB)
#define SB_LO     (3 * 128 * ROWB)
#define STAGE_B   (4 * 128 * ROWB)         // 32768
#define NSTAGE    3
#define SMEM_TOTAL (NSTAGE * STAGE_B)      // 98304 (x2 CTAs = 192KB)
#define PANEL_W   8

struct GemmArgs {
    const __nv_bfloat16 *Ah, *Al, *Bh, *Bl;
    int K;
    float* C; int M;
    const __nv_bfloat16 *B2h, *B2l;   // DUAL second B
    float* C2; int msplit;            // DUAL second C, bx split point
    const float* G;                   // EPI=2 gate tile source
    __nv_bfloat16 *Oh, *Ol;           // EPI=1/2 bf16 hi/lo outputs
};

template <int EPI, int DUAL, int BETA>
__global__ void __launch_bounds__(256, 2)
tc_gemm(GemmArgs a)
{
    extern __shared__ char smem[];
    const uint32_t sb = smem_u32(smem);
    const int t    = threadIdx.x;
    const int lane = t & 31;
    const int w    = t >> 5;
    const int wm   = w >> 2;
    const int wn   = w & 3;

    // ---- panel-swizzled CTA mapping ----
    int bx, by;
    {
        const int gx = gridDim.x, gy = gridDim.y;
        int bid = blockIdx.y * gx + blockIdx.x;
        int fp  = gx / PANEL_W;
        int rem = gx - fp * PANEL_W;
        int cf  = fp * PANEL_W * gy;
        if (bid < cf) {
            int p = bid / (PANEL_W * gy);
            int r = bid - p * (PANEL_W * gy);
            bx = p * PANEL_W + (r % PANEL_W);
            by = r / PANEL_W;
        } else {
            int r = bid - cf;
            bx = fp * PANEL_W + (r % rem);
            by = r / rem;
        }
    }

    bool alt = false;
    if (DUAL && bx >= a.msplit) { alt = true; bx -= a.msplit; }

    const __nv_bfloat16* BhS = (DUAL && alt) ? a.B2h : a.Bh;
    const __nv_bfloat16* BlS = (DUAL && alt) ? a.B2l : a.Bl;

    const int K = a.K;
    const size_t rs = (size_t)K * 2;
    const char* Ah = (const char*)a.Ah + (size_t)by * 128 * rs;
    const char* Al = (const char*)a.Al + (size_t)by * 128 * rs;
    const char* Bh = (const char*)BhS + (size_t)bx * 128 * rs;
    const char* Bl = (const char*)BlS + (size_t)bx * 128 * rs;

    const int KB = K / BK;

    int r0 = t >> 2, c0 = t & 3;
    int r1 = r0 + 64;
    int cs = c0 ^ ((r0 >> 1) & 3);
    uint32_t so0 = (uint32_t)r0 * ROWB + cs * 16;
    uint32_t so1 = (uint32_t)r1 * ROWB + cs * 16;
    size_t   go0 = (size_t)r0 * rs + c0 * 16;
    size_t   go1 = (size_t)r1 * rs + c0 * 16;

#define LOAD_STAGE(kb, buf)                                                  \
    do {                                                                     \
        uint32_t st = sb + (uint32_t)(buf) * STAGE_B;                        \
        size_t   kofs = (size_t)(kb) * 64;                                   \
        cpasync16(st + SA_HI + so0, Ah + go0 + kofs);                        \
        cpasync16(st + SA_HI + so1, Ah + go1 + kofs);                        \
        cpasync16(st + SA_LO + so0, Al + go0 + kofs);                        \
        cpasync16(st + SA_LO + so1, Al + go1 + kofs);                        \
        cpasync16(st + SB_HI + so0, Bh + go0 + kofs);                        \
        cpasync16(st + SB_HI + so1, Bh + go1 + kofs);                        \
        cpasync16(st + SB_LO + so0, Bl + go0 + kofs);                        \
        cpasync16(st + SB_LO + so1, Bl + go1 + kofs);                        \
        cp_commit();                                                         \
    } while (0)

    const int la_r  = lane & 15;
    const int la_sw = (la_r >> 1) & 3;
    const int la_c  = lane >> 4;
    const int lb_r  = (lane & 7) + ((lane >> 4) << 3);
    const int lb_sw = (lb_r >> 1) & 3;
    const int lb_c  = (lane >> 3) & 1;

    float acc[4][4][4];
#pragma unroll
    for (int mi = 0; mi < 4; mi++)
#pragma unroll
        for (int ni = 0; ni < 4; ni++)
#pragma unroll
            for (int q = 0; q < 4; q++) acc[mi][ni][q] = 0.f;

    LOAD_STAGE(0, 0);
    LOAD_STAGE(1, 1);

    int buf = 0, nbuf = 2;
    for (int kb = 0; kb < KB; kb++) {
        if (kb + 1 < KB) cp_wait<1>(); else cp_wait<0>();
        __syncthreads();
        if (kb + 2 < KB) LOAD_STAGE(kb + 2, nbuf);

        const uint32_t st = sb + (uint32_t)buf * STAGE_B;
#pragma unroll
        for (int kk = 0; kk < 2; kk++) {
            const uint32_t ca = (uint32_t)((kk * 2 + la_c) ^ la_sw) * 16;
            const uint32_t cb = (uint32_t)((kk * 2 + lb_c) ^ lb_sw) * 16;
            uint32_t bhf[2][4], blf[2][4];
#pragma unroll
            for (int pr = 0; pr < 2; pr++) {
                uint32_t base = (uint32_t)(wn * 32 + pr * 16 + lb_r) * ROWB + cb;
                ldm4(bhf[pr], st + SB_HI + base);
                ldm4(blf[pr], st + SB_LO + base);
            }
#pragma unroll
            for (int mi = 0; mi < 4; mi++) {
                uint32_t ah[4], al[4];
                uint32_t base = (uint32_t)(wm * 64 + mi * 16 + la_r) * ROWB + ca;
                ldm4(ah, st + SA_HI + base);
                ldm4(al, st + SA_LO + base);
#pragma unroll
                for (int ni = 0; ni < 4; ni++) {
                    const int pr = ni >> 1, hf = (ni & 1) * 2;
                    mma16816(acc[mi][ni], ah, bhf[pr][hf], bhf[pr][hf + 1]);
                    mma16816(acc[mi][ni], ah, blf[pr][hf], blf[pr][hf + 1]);
                    mma16816(acc[mi][ni], al, bhf[pr][hf], bhf[pr][hf + 1]);
                }
            }
        }
        buf  = (buf  == 2) ? 0 : buf + 1;
        nbuf = (nbuf == 2) ? 0 : nbuf + 1;
    }
#undef LOAD_STAGE

    // ---- epilogue ----
    const int M = a.M;
    const int erow = by * 128 + wm * 64 + (lane >> 2);
    const int ecol = bx * 128 + wn * 32 + (lane & 3) * 2;
    float* CS = (DUAL && alt) ? a.C2 : a.C;

#pragma unroll
    for (int mi = 0; mi < 4; mi++) {
#pragma unroll
        for (int ni = 0; ni < 4; ni++) {
            const int row = erow + mi * 16;
            const int col = ecol + ni * 8;
            float q0 = acc[mi][ni][0], q1 = acc[mi][ni][1];
            float q2 = acc[mi][ni][2], q3 = acc[mi][ni][3];
            if (EPI == 2) {
                float2 g0 = *(const float2*)(a.G + (size_t)row * M + col);
                float2 g1 = *(const float2*)(a.G + (size_t)(row + 8) * M + col);
                float p0 = silu_mul(g0.x, q0), p1 = silu_mul(g0.y, q1);
                float p2 = silu_mul(g1.x, q2), p3 = silu_mul(g1.y, q3);
                uint32_t h0 = cvt_bf16x2(p0, p1);
                uint32_t h1 = cvt_bf16x2(p2, p3);
                *(uint32_t*)(a.Oh + (size_t)row * M + col)       = h0;
                *(uint32_t*)(a.Oh + (size_t)(row + 8) * M + col) = h1;
                uint32_t l0 = cvt_bf16x2(p0 - bf_lo_f(h0), p1 - bf_hi_f(h0));
                uint32_t l1 = cvt_bf16x2(p2 - bf_lo_f(h1), p3 - bf_hi_f(h1));
                *(uint32_t*)(a.Ol + (size_t)row * M + col)       = l0;
                *(uint32_t*)(a.Ol + (size_t)(row + 8) * M + col) = l1;
            } else {
                float2* p0p = (float2*)(CS + (size_t)row * M + col);
                float2* p1p = (float2*)(CS + (size_t)(row + 8) * M + col);
                if (BETA) {
                    float2 o0 = *p0p, o1 = *p1p;
                    q0 += o0.x; q1 += o0.y; q2 += o1.x; q3 += o1.y;
                }
                *p0p = make_float2(q0, q1);
                *p1p = make_float2(q2, q3);
                if (EPI == 1 && !alt) {
                    uint32_t h0 = cvt_bf16x2(q0, q1);
                    uint32_t h1 = cvt_bf16x2(q2, q3);
                    *(uint32_t*)(a.Oh + (size_t)row * M + col)       = h0;
                    *(uint32_t*)(a.Oh + (size_t)(row + 8) * M + col) = h1;
                    uint32_t l0 = cvt_bf16x2(q0 - bf_lo_f(h0), q1 - bf_hi_f(h0));
                    uint32_t l1 = cvt_bf16x2(q2 - bf_lo_f(h1), q3 - bf_hi_f(h1));
                    *(uint32_t*)(a.Ol + (size_t)row * M + col)       = l0;
                    *(uint32_t*)(a.Ol + (size_t)(row + 8) * M + col) = l1;
                }
            }
        }
    }
}

// ---------------------------------------------------------------------------
// fp32 -> (hi, lo) bf16 split. Unit = 2 float4 (8 elems); 4 units/thread.
// ---------------------------------------------------------------------------
__global__ void split8(const float4* __restrict__ src,
                       uint4* __restrict__ hi, uint4* __restrict__ lo, int n8)
{
    int u0 = blockIdx.x * (blockDim.x * 4) + threadIdx.x;
    float4 a[4], b[4];
    bool   ok[4];
#pragma unroll
    for (int j = 0; j < 4; j++) {
        int u = u0 + j * 256;
        ok[j] = (u < n8);
        if (ok[j]) { a[j] = src[2 * (size_t)u]; b[j] = src[2 * (size_t)u + 1]; }
    }
#pragma unroll
    for (int j = 0; j < 4; j++) {
        if (!ok[j]) continue;
        int u = u0 + j * 256;
        uint32_t h0 = cvt_bf16x2(a[j].x, a[j].y);
        uint32_t h1 = cvt_bf16x2(a[j].z, a[j].w);
        uint32_t h2 = cvt_bf16x2(b[j].x, b[j].y);
        uint32_t h3 = cvt_bf16x2(b[j].z, b[j].w);
        hi[u] = make_uint4(h0, h1, h2, h3);
        uint32_t l0 = cvt_bf16x2(a[j].x - bf_lo_f(h0), a[j].y - bf_hi_f(h0));
        uint32_t l1 = cvt_bf16x2(a[j].z - bf_lo_f(h1), a[j].w - bf_hi_f(h1));
        uint32_t l2 = cvt_bf16x2(b[j].x - bf_lo_f(h2), b[j].y - bf_hi_f(h2));
        uint32_t l3 = cvt_bf16x2(b[j].z - bf_lo_f(h3), b[j].w - bf_hi_f(h3));
        lo[u] = make_uint4(l0, l1, l2, l3);
    }
}

// ---------------------------------------------------------------------------
// Taylor coefficients -> split bf16 TMP[t, s*6+g]
// ---------------------------------------------------------------------------
__global__ void taylor_kernel(const float* __restrict__ AU, const float* __restrict__ GP,
                              const float* __restrict__ lp, const float* __restrict__ df,
                              __nv_bfloat16* __restrict__ TMPh, __nv_bfloat16* __restrict__ TMPl)
{
    int idx = blockIdx.x * blockDim.x + threadIdx.x;    // t*1024 + s
    if (idx >= NTOK * SDIM) return;
    int s = idx & (SDIM - 1);

    float au    = AU[idx];
    float delta = GP[idx] - lp[s];
    float neg   = (delta > 0.f) ? 1.f : -1.f;
    float ad    = fabsf(delta);
    float ld    = logf(ad);
    float keep  = (ad <= 2.5f) ? 1.f : 0.f;

    float v[6];
#pragma unroll
    for (int g = 0; g < 6; g++) {
        int   m = g + 1;
        float dterm = expf(ld * (float)m - df[g]);
        if (m & 1) dterm *= neg;
        float x = dterm * au;
        if (m > 4) x *= keep;
        v[g] = x;
    }
    uint32_t h[3], l[3];
#pragma unroll
    for (int q = 0; q < 3; q++) {
        h[q] = cvt_bf16x2(v[2 * q], v[2 * q + 1]);
        l[q] = cvt_bf16x2(v[2 * q] - bf_lo_f(h[q]), v[2 * q + 1] - bf_hi_f(h[q]));
    }
    uint32_t* ph = (uint32_t*)(TMPh + (size_t)idx * 6);
    uint32_t* pl = (uint32_t*)(TMPl + (size_t)idx * 6);
    ph[0] = h[0]; ph[1] = h[1]; ph[2] = h[2];
    pl[0] = l[0]; pl[1] = l[1]; pl[2] = l[2];
}

// ---------------------------------------------------------------------------
// kernel_launch
// ---------------------------------------------------------------------------
static inline void run_split(const float* src, __nv_bfloat16* hi, __nv_bfloat16* lo, size_t n) {
    int n8 = (int)(n >> 3);
    split8<<<(n8 + 1023) / 1024, 256>>>((const float4*)src, (uint4*)hi, (uint4*)lo, n8);
}

extern "C" void kernel_launch(void* const* d_in, const int* in_sizes, int n_in,
                              void* d_out, int out_size)
{
    const float* X   = (const float*)d_in[0];   // [4096,4096]
    const float* upw = (const float*)d_in[1];   // [1024,4096]
    const float* gw  = (const float*)d_in[2];   // [1024,4096]
    const float* lp  = (const float*)d_in[3];   // [1024]
    const float* lao = (const float*)d_in[4];   // [4096,1024]
    const float* fw  = (const float*)d_in[5];   // [4096,6144]
    const float* df  = (const float*)d_in[6];   // [6]
    const float* fgw = (const float*)d_in[7];   // [9984,4096]
    const float* fuw = (const float*)d_in[8];   // [9984,4096]
    const float* fdw = (const float*)d_in[9];   // [4096,9984]
    float* out       = (float*)d_out;           // [4096,4096]

    cudaFuncSetAttribute(tc_gemm<0, 0, 0>, cudaFuncAttributeMaxDynamicSharedMemorySize, SMEM_TOTAL);
    cudaFuncSetAttribute(tc_gemm<0, 0, 1>, cudaFuncAttributeMaxDynamicSharedMemorySize, SMEM_TOTAL);
    cudaFuncSetAttribute(tc_gemm<1, 1, 0>, cudaFuncAttributeMaxDynamicSharedMemorySize, SMEM_TOTAL);
    cudaFuncSetAttribute(tc_gemm<2, 0, 0>, cudaFuncAttributeMaxDynamicSharedMemorySize, SMEM_TOTAL);

#define SYM(p, s) cudaGetSymbolAddress((void**)&p, s)
    __nv_bfloat16 *Xh, *Xl, *upwh, *upwl, *gwh, *gwl, *laoh, *laol, *fwh, *fwl;
    __nv_bfloat16 *fgwh, *fgwl, *fuwh, *fuwl, *fdwh, *fdwl;
    __nv_bfloat16 *AUh, *AUl, *TMPh, *TMPl, *Ph, *Pl;
    float *AU, *GP, *BG;
    SYM(Xh, g_Xhi);   SYM(Xl, g_Xlo);
    SYM(upwh, g_upwh); SYM(upwl, g_upwl);
    SYM(gwh, g_gwh);   SYM(gwl, g_gwl);
    SYM(laoh, g_laoh); SYM(laol, g_laol);
    SYM(fwh, g_fwh);   SYM(fwl, g_fwl);
    SYM(fgwh, g_fgwh); SYM(fgwl, g_fgwl);
    SYM(fuwh, g_fuwh); SYM(fuwl, g_fuwl);
    SYM(fdwh, g_fdwh); SYM(fdwl, g_fdwl);
    SYM(AU, g_AU);     SYM(GP, g_GP);
    SYM(AUh, g_AUh);   SYM(AUl, g_AUl);
    SYM(TMPh, g_TMPh); SYM(TMPl, g_TMPl);
    SYM(BG, g_BG);
    SYM(Ph, g_Ph);     SYM(Pl, g_Pl);
#undef SYM

    // --- fp32 -> hi/lo bf16 conversions (inputs only) ---
    run_split(X,   Xh,   Xl,   (size_t)NTOK * HDIM);
    run_split(upw, upwh, upwl, (size_t)SDIM * HDIM);
    run_split(gw,  gwh,  gwl,  (size_t)SDIM * HDIM);
    run_split(lao, laoh, laol, (size_t)HDIM * SDIM);
    run_split(fw,  fwh,  fwl,  (size_t)HDIM * KTAY);
    run_split(fgw, fgwh, fgwl, (size_t)FDIM * HDIM);
    run_split(fuw, fuwh, fuwl, (size_t)FDIM * HDIM);
    run_split(fdw, fdwh, fdwl, (size_t)HDIM * FDIM);

    GemmArgs a{};

    // 1+2 merged (DUAL, EPI=1): AU = X@up_w^T (AUh/AUl fused in epilogue),
    // GP = X@gate_w^T. grid (16, 32).
    a = GemmArgs{};
    a.Ah = Xh; a.Al = Xl; a.Bh = upwh; a.Bl = upwl; a.K = HDIM;
    a.C = AU; a.M = SDIM;
    a.B2h = gwh; a.B2l = gwl; a.C2 = GP; a.msplit = SDIM / 128;
    a.Oh = AUh; a.Ol = AUl;
    tc_gemm<1, 1, 0><<<dim3(2 * SDIM / 128, NTOK / 128), 256, SMEM_TOTAL>>>(a);

    // 3: Taylor coefficients -> TMP hi/lo
    taylor_kernel<<<(NTOK * SDIM) / 256, 256>>>(AU, GP, lp, df, TMPh, TMPl);

    // 4: out = AU @ lao^T
    a = GemmArgs{};
    a.Ah = AUh; a.Al = AUl; a.Bh = laoh; a.Bl = laol; a.K = SDIM;
    a.C = out; a.M = HDIM;
    tc_gemm<0, 0, 0><<<dim3(HDIM / 128, NTOK / 128), 256, SMEM_TOTAL>>>(a);

    // 5: out += TMP @ fw^T
    a = GemmArgs{};
    a.Ah = TMPh; a.Al = TMPl; a.Bh = fwh; a.Bl = fwl; a.K = KTAY;
    a.C = out; a.M = HDIM;
    tc_gemm<0, 0, 1><<<dim3(HDIM / 128, NTOK / 128), 256, SMEM_TOTAL>>>(a);

    // 6: FFN gate -> BG (fp32)
    a = GemmArgs{};
    a.Ah = Xh; a.Al = Xl; a.Bh = fgwh; a.Bl = fgwl; a.K = HDIM;
    a.C = BG; a.M = FDIM;
    tc_gemm<0, 0, 0><<<dim3(FDIM / 128, NTOK / 128), 256, SMEM_TOTAL>>>(a);

    // 7: FFN up with fused silu epilogue: P = silu(BG) * (X@fuw^T) -> Ph/Pl
    a = GemmArgs{};
    a.Ah = Xh; a.Al = Xl; a.Bh = fuwh; a.Bl = fuwl; a.K = HDIM;
    a.M = FDIM; a.G = BG; a.Oh = Ph; a.Ol = Pl;
    tc_gemm<2, 0, 0><<<dim3(FDIM / 128, NTOK / 128), 256, SMEM_TOTAL>>>(a);

    // 9: out += P @ fdw^T
    a = GemmArgs{};
    a.Ah = Ph; a.Al = Pl; a.Bh = fdwh; a.Bl = fdwl; a.K = FDIM;
    a.C = out; a.M = HDIM;
    tc_gemm<0, 0, 1><<<dim3(HDIM / 128, NTOK / 128), 256, SMEM_TOTAL>>>(a);
}

// round 15
// speedup vs baseline: 1.0532x; 1.0486x over previous
#include <cuda_runtime.h>
#include <cuda_bf16.h>
#include <cstdint>

// ---------------------------------------------------------------------------
// Shapes (fixed)
// ---------------------------------------------------------------------------
#define NTOK 4096            // B*T
#define HDIM 4096
#define SDIM 1024
#define FDIM 9984
#define KTAY 6144            // S*G

// ---------------------------------------------------------------------------
// Scratch (__device__ globals; allocation-free)
// ---------------------------------------------------------------------------
__device__ __nv_bfloat16 g_Xhi [NTOK * HDIM], g_Xlo [NTOK * HDIM];
__device__ __nv_bfloat16 g_upwh[SDIM * HDIM], g_upwl[SDIM * HDIM];
__device__ __nv_bfloat16 g_gwh [SDIM * HDIM], g_gwl [SDIM * HDIM];
__device__ __nv_bfloat16 g_laoh[HDIM * SDIM], g_laol[HDIM * SDIM];
__device__ __nv_bfloat16 g_fwh [HDIM * KTAY], g_fwl [HDIM * KTAY];
__device__ __nv_bfloat16 g_fgwh[(size_t)FDIM * HDIM], g_fgwl[(size_t)FDIM * HDIM];
__device__ __nv_bfloat16 g_fuwh[(size_t)FDIM * HDIM], g_fuwl[(size_t)FDIM * HDIM];
__device__ __nv_bfloat16 g_fdwh[(size_t)HDIM * FDIM], g_fdwl[(size_t)HDIM * FDIM];
__device__ float         g_AU  [NTOK * SDIM], g_GP  [NTOK * SDIM];
__device__ __nv_bfloat16 g_AUh [NTOK * SDIM], g_AUl [NTOK * SDIM];
__device__ __nv_bfloat16 g_TMPh[NTOK * KTAY], g_TMPl[NTOK * KTAY];
__device__ float         g_BG  [(size_t)NTOK * FDIM];
__device__ __nv_bfloat16 g_Ph  [(size_t)NTOK * FDIM], g_Pl[(size_t)NTOK * FDIM];

// ---------------------------------------------------------------------------
// Baseline-PTX helpers
// ---------------------------------------------------------------------------
__device__ __forceinline__ uint32_t smem_u32(const void* p) {
    uint32_t a;
    asm("{ .reg .u64 t; cvta.to.shared.u64 t, %1; cvt.u32.u64 %0, t; }" : "=r"(a) : "l"(p));
    return a;
}
__device__ __forceinline__ void cpasync16(uint32_t dst, const void* src) {
    asm volatile("cp.async.cg.shared.global [%0], [%1], 16;" :: "r"(dst), "l"(src) : "memory");
}
__device__ __forceinline__ void cp_commit() {
    asm volatile("cp.async.commit_group;" ::: "memory");
}
template <int N>
__device__ __forceinline__ void cp_wait() {
    asm volatile("cp.async.wait_group %0;" :: "n"(N) : "memory");
}
__device__ __forceinline__ void ldm4(uint32_t* r, uint32_t a) {
    asm volatile("ldmatrix.sync.aligned.m8n8.x4.shared.b16 {%0,%1,%2,%3}, [%4];"
                 : "=r"(r[0]), "=r"(r[1]), "=r"(r[2]), "=r"(r[3]) : "r"(a));
}
__device__ __forceinline__ void mma16816(float* d, const uint32_t* a, uint32_t b0, uint32_t b1) {
    asm volatile("mma.sync.aligned.m16n8k16.row.col.f32.bf16.bf16.f32 "
                 "{%0,%1,%2,%3}, {%4,%5,%6,%7}, {%8,%9}, {%0,%1,%2,%3};"
                 : "+f"(d[0]), "+f"(d[1]), "+f"(d[2]), "+f"(d[3])
                 : "r"(a[0]), "r"(a[1]), "r"(a[2]), "r"(a[3]), "r"(b0), "r"(b1));
}
__device__ __forceinline__ uint32_t cvt_bf16x2(float lo_el, float hi_el) {
    uint32_t r;
    asm("cvt.rn.bf16x2.f32 %0, %1, %2;" : "=r"(r) : "f"(hi_el), "f"(lo_el));
    return r;
}
__device__ __forceinline__ float bf_lo_f(uint32_t p) { return __uint_as_float(p << 16); }
__device__ __forceinline__ float bf_hi_f(uint32_t p) { return __uint_as_float(p & 0xffff0000u); }
__device__ __forceinline__ float silu_mul(float g, float u) {
    return g / (1.f + expf(-g)) * u;
}

// ---------------------------------------------------------------------------
// Split-bf16 tensor-core GEMM (3-pass: Ah*Bh + Ah*Bl + Al*Bh, fp32 accum).
// History constraints: 2-pass (R10) -> 1.74e-3, over threshold; vertical
// K-merge (R13) -> +280us; both permanently reverted.
// R15: horizontal merge — one launch carries up to TWO independent GEMMs;
// each CTA runs ONE single-segment mainloop, selected by bid threshold.
// Epilogue variant (epi) and accumulate flag (beta) are runtime fields.
//   epi 0: fp32 C (+= if beta)
//   epi 1: dual-proj: fp32 C/C2 (by msplit); primary path also emits Oh/Ol
//   epi 2: silu: p = silu(G_tile) * acc -> Oh/Ol only
// CTA tile 128x128, BK=32, 256 thr, warp tile 64x32, 3-stage cp.async ring,
// one __syncthreads per k-block, 2 CTAs/SM, XOR-swizzled 64B SMEM rows,
// panel-swizzled tile map. Requires M%128==0, K%32==0.
// ---------------------------------------------------------------------------
#define BK        32
#define ROWB      64
#define SA_HI     0
#define SA_LO     (128 * ROWB)
#define SB_HI     (2 * 128 * ROWB)
#define SB_LO     (3 * 128 * ROWB)
#define STAGE_B   (4 * 128 * ROWB)         // 32768
#define NSTAGE    3
#define SMEM_TOTAL (NSTAGE * STAGE_B)      // 98304 (x2 CTAs = 192KB)
#define PANEL_W   8

struct GArg {
    const __nv_bfloat16 *Ah, *Al, *Bh, *Bl;
    const __nv_bfloat16 *B2h, *B2l;   // epi=1 second B
    float *C, *C2;
    const float* G;                   // epi=2 gate source
    __nv_bfloat16 *Oh, *Ol;           // epi=1/2 bf16 outputs
    int K, M, gx, gy, msplit, epi, beta;
};
struct GPair { GArg s0, s1; int nb0; };

__global__ void __launch_bounds__(256, 2)
tc_gemm(GPair p)
{
    extern __shared__ char smem[];
    const uint32_t sb = smem_u32(smem);
    const int t    = threadIdx.x;
    const int lane = t & 31;
    const int w    = t >> 5;
    const int wm   = w >> 2;
    const int wn   = w & 3;

    int bid = blockIdx.x;
    const GArg* ap = &p.s0;
    if (bid >= p.nb0) { ap = &p.s1; bid -= p.nb0; }
    const GArg a = *ap;

    // ---- panel-swizzled tile mapping (within this segment's gx x gy) ----
    int bx, by;
    {
        const int gx = a.gx, gy = a.gy;
        int fp  = gx / PANEL_W;
        int rem = gx - fp * PANEL_W;
        int cf  = fp * PANEL_W * gy;
        if (bid < cf) {
            int pp = bid / (PANEL_W * gy);
            int r  = bid - pp * (PANEL_W * gy);
            bx = pp * PANEL_W + (r % PANEL_W);
            by = r / PANEL_W;
        } else {
            int r = bid - cf;
            bx = fp * PANEL_W + (r % rem);
            by = r / rem;
        }
    }

    bool alt = false;
    if (bx >= a.msplit) { alt = true; bx -= a.msplit; }

    const __nv_bfloat16* BhS = alt ? a.B2h : a.Bh;
    const __nv_bfloat16* BlS = alt ? a.B2l : a.Bl;

    const int K = a.K;
    const size_t rs = (size_t)K * 2;
    const char* Ah = (const char*)a.Ah + (size_t)by * 128 * rs;
    const char* Al = (const char*)a.Al + (size_t)by * 128 * rs;
    const char* Bh = (const char*)BhS + (size_t)bx * 128 * rs;
    const char* Bl = (const char*)BlS + (size_t)bx * 128 * rs;

    const int KB = K / BK;

    int r0 = t >> 2, c0 = t & 3;
    int r1 = r0 + 64;
    int cs = c0 ^ ((r0 >> 1) & 3);
    uint32_t so0 = (uint32_t)r0 * ROWB + cs * 16;
    uint32_t so1 = (uint32_t)r1 * ROWB + cs * 16;
    size_t   go0 = (size_t)r0 * rs + c0 * 16;
    size_t   go1 = (size_t)r1 * rs + c0 * 16;

#define LOAD_STAGE(kb, buf)                                                  \
    do {                                                                     \
        uint32_t st = sb + (uint32_t)(buf) * STAGE_B;                        \
        size_t   kofs = (size_t)(kb) * 64;                                   \
        cpasync16(st + SA_HI + so0, Ah + go0 + kofs);                        \
        cpasync16(st + SA_HI + so1, Ah + go1 + kofs);                        \
        cpasync16(st + SA_LO + so0, Al + go0 + kofs);                        \
        cpasync16(st + SA_LO + so1, Al + go1 + kofs);                        \
        cpasync16(st + SB_HI + so0, Bh + go0 + kofs);                        \
        cpasync16(st + SB_HI + so1, Bh + go1 + kofs);                        \
        cpasync16(st + SB_LO + so0, Bl + go0 + kofs);                        \
        cpasync16(st + SB_LO + so1, Bl + go1 + kofs);                        \
        cp_commit();                                                         \
    } while (0)

    const int la_r  = lane & 15;
    const int la_sw = (la_r >> 1) & 3;
    const int la_c  = lane >> 4;
    const int lb_r  = (lane & 7) + ((lane >> 4) << 3);
    const int lb_sw = (lb_r >> 1) & 3;
    const int lb_c  = (lane >> 3) & 1;

    float acc[4][4][4];
#pragma unroll
    for (int mi = 0; mi < 4; mi++)
#pragma unroll
        for (int ni = 0; ni < 4; ni++)
#pragma unroll
            for (int q = 0; q < 4; q++) acc[mi][ni][q] = 0.f;

    LOAD_STAGE(0, 0);
    LOAD_STAGE(1, 1);

    int buf = 0, nbuf = 2;
    for (int kb = 0; kb < KB; kb++) {
        if (kb + 1 < KB) cp_wait<1>(); else cp_wait<0>();
        __syncthreads();
        if (kb + 2 < KB) LOAD_STAGE(kb + 2, nbuf);

        const uint32_t st = sb + (uint32_t)buf * STAGE_B;
#pragma unroll
        for (int kk = 0; kk < 2; kk++) {
            const uint32_t ca = (uint32_t)((kk * 2 + la_c) ^ la_sw) * 16;
            const uint32_t cb = (uint32_t)((kk * 2 + lb_c) ^ lb_sw) * 16;
            uint32_t bhf[2][4], blf[2][4];
#pragma unroll
            for (int pr = 0; pr < 2; pr++) {
                uint32_t base = (uint32_t)(wn * 32 + pr * 16 + lb_r) * ROWB + cb;
                ldm4(bhf[pr], st + SB_HI + base);
                ldm4(blf[pr], st + SB_LO + base);
            }
#pragma unroll
            for (int mi = 0; mi < 4; mi++) {
                uint32_t ah[4], al[4];
                uint32_t base = (uint32_t)(wm * 64 + mi * 16 + la_r) * ROWB + ca;
                ldm4(ah, st + SA_HI + base);
                ldm4(al, st + SA_LO + base);
#pragma unroll
                for (int ni = 0; ni < 4; ni++) {
                    const int pr = ni >> 1, hf = (ni & 1) * 2;
                    mma16816(acc[mi][ni], ah, bhf[pr][hf], bhf[pr][hf + 1]);
                    mma16816(acc[mi][ni], ah, blf[pr][hf], blf[pr][hf + 1]);
                    mma16816(acc[mi][ni], al, bhf[pr][hf], bhf[pr][hf + 1]);
                }
            }
        }
        buf  = (buf  == 2) ? 0 : buf + 1;
        nbuf = (nbuf == 2) ? 0 : nbuf + 1;
    }
#undef LOAD_STAGE

    // ---- epilogue (runtime variant) ----
    const int M = a.M;
    const int erow = by * 128 + wm * 64 + (lane >> 2);
    const int ecol = bx * 128 + wn * 32 + (lane & 3) * 2;
    float* CS = alt ? a.C2 : a.C;

#pragma unroll
    for (int mi = 0; mi < 4; mi++) {
#pragma unroll
        for (int ni = 0; ni < 4; ni++) {
            const int row = erow + mi * 16;
            const int col = ecol + ni * 8;
            float q0 = acc[mi][ni][0], q1 = acc[mi][ni][1];
            float q2 = acc[mi][ni][2], q3 = acc[mi][ni][3];
            if (a.epi == 2) {
                float2 g0 = *(const float2*)(a.G + (size_t)row * M + col);
                float2 g1 = *(const float2*)(a.G + (size_t)(row + 8) * M + col);
                float p0 = silu_mul(g0.x, q0), p1 = silu_mul(g0.y, q1);
                float p2 = silu_mul(g1.x, q2), p3 = silu_mul(g1.y, q3);
                uint32_t h0 = cvt_bf16x2(p0, p1);
                uint32_t h1 = cvt_bf16x2(p2, p3);
                *(uint32_t*)(a.Oh + (size_t)row * M + col)       = h0;
                *(uint32_t*)(a.Oh + (size_t)(row + 8) * M + col) = h1;
                uint32_t l0 = cvt_bf16x2(p0 - bf_lo_f(h0), p1 - bf_hi_f(h0));
                uint32_t l1 = cvt_bf16x2(p2 - bf_lo_f(h1), p3 - bf_hi_f(h1));
                *(uint32_t*)(a.Ol + (size_t)row * M + col)       = l0;
                *(uint32_t*)(a.Ol + (size_t)(row + 8) * M + col) = l1;
            } else {
                float2* p0p = (float2*)(CS + (size_t)row * M + col);
                float2* p1p = (float2*)(CS + (size_t)(row + 8) * M + col);
                if (a.beta) {
                    float2 o0 = *p0p, o1 = *p1p;
                    q0 += o0.x; q1 += o0.y; q2 += o1.x; q3 += o1.y;
                }
                *p0p = make_float2(q0, q1);
                *p1p = make_float2(q2, q3);
                if (a.epi == 1 && !alt) {
                    uint32_t h0 = cvt_bf16x2(q0, q1);
                    uint32_t h1 = cvt_bf16x2(q2, q3);
                    *(uint32_t*)(a.Oh + (size_t)row * M + col)       = h0;
                    *(uint32_t*)(a.Oh + (size_t)(row + 8) * M + col) = h1;
                    uint32_t l0 = cvt_bf16x2(q0 - bf_lo_f(h0), q1 - bf_hi_f(h0));
                    uint32_t l1 = cvt_bf16x2(q2 - bf_lo_f(h1), q3 - bf_hi_f(h1));
                    *(uint32_t*)(a.Ol + (size_t)row * M + col)       = l0;
                    *(uint32_t*)(a.Ol + (size_t)(row + 8) * M + col) = l1;
                }
            }
        }
    }
}

// ---------------------------------------------------------------------------
// Merged fp32 -> (hi, lo) bf16 split: all 8 buffers in ONE launch.
// Unit = 2 float4 (8 elems); 4 units/thread; 1024 units per block.
// ---------------------------------------------------------------------------
#define NSPLIT 8
struct SplitTab {
    const float4* src[NSPLIT];
    uint4* hi[NSPLIT];
    uint4* lo[NSPLIT];
    int end[NSPLIT];     // prefix-sum of block counts
    int n8[NSPLIT];
};

__global__ void split_all(SplitTab tb)
{
    int b = blockIdx.x;
    int s = 0;
    while (s < NSPLIT - 1 && b >= tb.end[s]) s++;
    int lb = b - (s ? tb.end[s - 1] : 0);
    const int n8 = tb.n8[s];
    const float4* src = tb.src[s];
    uint4* hi = tb.hi[s];
    uint4* lo = tb.lo[s];

    int u0 = lb * 1024 + threadIdx.x;
    float4 a[4], c[4];
    bool   ok[4];
#pragma unroll
    for (int j = 0; j < 4; j++) {
        int u = u0 + j * 256;
        ok[j] = (u < n8);
        if (ok[j]) { a[j] = src[2 * (size_t)u]; c[j] = src[2 * (size_t)u + 1]; }
    }
#pragma unroll
    for (int j = 0; j < 4; j++) {
        if (!ok[j]) continue;
        int u = u0 + j * 256;
        uint32_t h0 = cvt_bf16x2(a[j].x, a[j].y);
        uint32_t h1 = cvt_bf16x2(a[j].z, a[j].w);
        uint32_t h2 = cvt_bf16x2(c[j].x, c[j].y);
        uint32_t h3 = cvt_bf16x2(c[j].z, c[j].w);
        hi[u] = make_uint4(h0, h1, h2, h3);
        uint32_t l0 = cvt_bf16x2(a[j].x - bf_lo_f(h0), a[j].y - bf_hi_f(h0));
        uint32_t l1 = cvt_bf16x2(a[j].z - bf_lo_f(h1), a[j].w - bf_hi_f(h1));
        uint32_t l2 = cvt_bf16x2(c[j].x - bf_lo_f(h2), c[j].y - bf_hi_f(h2));
        uint32_t l3 = cvt_bf16x2(c[j].z - bf_lo_f(h3), c[j].w - bf_hi_f(h3));
        lo[u] = make_uint4(l0, l1, l2, l3);
    }
}

// ---------------------------------------------------------------------------
// Taylor coefficients -> split bf16 TMP[t, s*6+g]
// ---------------------------------------------------------------------------
__global__ void taylor_kernel(const float* __restrict__ AU, const float* __restrict__ GP,
                              const float* __restrict__ lp, const float* __restrict__ df,
                              __nv_bfloat16* __restrict__ TMPh, __nv_bfloat16* __restrict__ TMPl)
{
    int idx = blockIdx.x * blockDim.x + threadIdx.x;    // t*1024 + s
    if (idx >= NTOK * SDIM) return;
    int s = idx & (SDIM - 1);

    float au    = AU[idx];
    float delta = GP[idx] - lp[s];
    float neg   = (delta > 0.f) ? 1.f : -1.f;
    float ad    = fabsf(delta);
    float ld    = logf(ad);
    float keep  = (ad <= 2.5f) ? 1.f : 0.f;

    float v[6];
#pragma unroll
    for (int g = 0; g < 6; g++) {
        int   m = g + 1;
        float dterm = expf(ld * (float)m - df[g]);
        if (m & 1) dterm *= neg;
        float x = dterm * au;
        if (m > 4) x *= keep;
        v[g] = x;
    }
    uint32_t h[3], l[3];
#pragma unroll
    for (int q = 0; q < 3; q++) {
        h[q] = cvt_bf16x2(v[2 * q], v[2 * q + 1]);
        l[q] = cvt_bf16x2(v[2 * q] - bf_lo_f(h[q]), v[2 * q + 1] - bf_hi_f(h[q]));
    }
    uint32_t* ph = (uint32_t*)(TMPh + (size_t)idx * 6);
    uint32_t* pl = (uint32_t*)(TMPl + (size_t)idx * 6);
    ph[0] = h[0]; ph[1] = h[1]; ph[2] = h[2];
    pl[0] = l[0]; pl[1] = l[1]; pl[2] = l[2];
}

// ---------------------------------------------------------------------------
// kernel_launch
// ---------------------------------------------------------------------------
extern "C" void kernel_launch(void* const* d_in, const int* in_sizes, int n_in,
                              void* d_out, int out_size)
{
    const float* X   = (const float*)d_in[0];   // [4096,4096]
    const float* upw = (const float*)d_in[1];   // [1024,4096]
    const float* gw  = (const float*)d_in[2];   // [1024,4096]
    const float* lp  = (const float*)d_in[3];   // [1024]
    const float* lao = (const float*)d_in[4];   // [4096,1024]
    const float* fw  = (const float*)d_in[5];   // [4096,6144]
    const float* df  = (const float*)d_in[6];   // [6]
    const float* fgw = (const float*)d_in[7];   // [9984,4096]
    const float* fuw = (const float*)d_in[8];   // [9984,4096]
    const float* fdw = (const float*)d_in[9];   // [4096,9984]
    float* out       = (float*)d_out;           // [4096,4096]

    cudaFuncSetAttribute(tc_gemm, cudaFuncAttributeMaxDynamicSharedMemorySize, SMEM_TOTAL);

#define SYM(p, s) cudaGetSymbolAddress((void**)&p, s)
    __nv_bfloat16 *Xh, *Xl, *upwh, *upwl, *gwh, *gwl, *laoh, *laol, *fwh, *fwl;
    __nv_bfloat16 *fgwh, *fgwl, *fuwh, *fuwl, *fdwh, *fdwl;
    __nv_bfloat16 *AUh, *AUl, *TMPh, *TMPl, *Ph, *Pl;
    float *AU, *GP, *BG;
    SYM(Xh, g_Xhi);   SYM(Xl, g_Xlo);
    SYM(upwh, g_upwh); SYM(upwl, g_upwl);
    SYM(gwh, g_gwh);   SYM(gwl, g_gwl);
    SYM(laoh, g_laoh); SYM(laol, g_laol);
    SYM(fwh, g_fwh);   SYM(fwl, g_fwl);
    SYM(fgwh, g_fgwh); SYM(fgwl, g_fgwl);
    SYM(fuwh, g_fuwh); SYM(fuwl, g_fuwl);
    SYM(fdwh, g_fdwh); SYM(fdwl, g_fdwl);
    SYM(AU, g_AU);     SYM(GP, g_GP);
    SYM(AUh, g_AUh);   SYM(AUl, g_AUl);
    SYM(TMPh, g_TMPh); SYM(TMPl, g_TMPl);
    SYM(BG, g_BG);
    SYM(Ph, g_Ph);     SYM(Pl, g_Pl);
#undef SYM

    // --- merged input split: one launch, 8 segments ---
    {
        SplitTab tb{};
        const float* srcs[NSPLIT] = {X, upw, gw, lao, fw, fgw, fuw, fdw};
        __nv_bfloat16* his[NSPLIT] = {Xh, upwh, gwh, laoh, fwh, fgwh, fuwh, fdwh};
        __nv_bfloat16* los[NSPLIT] = {Xl, upwl, gwl, laol, fwl, fgwl, fuwl, fdwl};
        size_t ns[NSPLIT] = {
            (size_t)NTOK * HDIM, (size_t)SDIM * HDIM, (size_t)SDIM * HDIM,
            (size_t)HDIM * SDIM, (size_t)HDIM * KTAY, (size_t)FDIM * HDIM,
            (size_t)FDIM * HDIM, (size_t)HDIM * FDIM};
        int total = 0;
        for (int i = 0; i < NSPLIT; i++) {
            tb.src[i] = (const float4*)srcs[i];
            tb.hi[i]  = (uint4*)his[i];
            tb.lo[i]  = (uint4*)los[i];
            tb.n8[i]  = (int)(ns[i] >> 3);
            total += (tb.n8[i] + 1023) / 1024;
            tb.end[i] = total;
        }
        split_all<<<total, 256>>>(tb);
    }

    GPair p{};
    GArg z{};   // zeroed defaults

    // Launch A — GEMM 1+2 (dual proj, epi=1): AU (+AUh/AUl) and GP.
    p = GPair{};
    p.s0 = z;
    p.s0.Ah = Xh; p.s0.Al = Xl; p.s0.Bh = upwh; p.s0.Bl = upwl;
    p.s0.B2h = gwh; p.s0.B2l = gwl;
    p.s0.C = AU; p.s0.C2 = GP; p.s0.Oh = AUh; p.s0.Ol = AUl;
    p.s0.K = HDIM; p.s0.M = SDIM; p.s0.gx = 16; p.s0.gy = NTOK / 128;
    p.s0.msplit = 8; p.s0.epi = 1; p.s0.beta = 0;
    p.s1 = p.s0;
    p.nb0 = 16 * (NTOK / 128);
    tc_gemm<<<p.nb0, 256, SMEM_TOTAL>>>(p);

    // Taylor coefficients -> TMP hi/lo
    taylor_kernel<<<(NTOK * SDIM) / 256, 256>>>(AU, GP, lp, df, TMPh, TMPl);

    // Launch B — {GEMM4: out = AU@lao^T} + {GEMM6: BG = X@fgw^T} (independent)
    p = GPair{};
    p.s0 = z;
    p.s0.Ah = AUh; p.s0.Al = AUl; p.s0.Bh = laoh; p.s0.Bl = laol;
    p.s0.C = out; p.s0.K = SDIM; p.s0.M = HDIM;
    p.s0.gx = HDIM / 128; p.s0.gy = NTOK / 128;
    p.s0.msplit = p.s0.gx; p.s0.epi = 0; p.s0.beta = 0;
    p.s1 = z;
    p.s1.Ah = Xh; p.s1.Al = Xl; p.s1.Bh = fgwh; p.s1.Bl = fgwl;
    p.s1.C = BG; p.s1.K = HDIM; p.s1.M = FDIM;
    p.s1.gx = FDIM / 128; p.s1.gy = NTOK / 128;
    p.s1.msplit = p.s1.gx; p.s1.epi = 0; p.s1.beta = 0;
    p.nb0 = (HDIM / 128) * (NTOK / 128);
    tc_gemm<<<p.nb0 + (FDIM / 128) * (NTOK / 128), 256, SMEM_TOTAL>>>(p);

    // Launch C — {GEMM5: out += TMP@fw^T} + {GEMM7: silu-fused up-proj}
    p = GPair{};
    p.s0 = z;
    p.s0.Ah = TMPh; p.s0.Al = TMPl; p.s0.Bh = fwh; p.s0.Bl = fwl;
    p.s0.C = out; p.s0.K = KTAY; p.s0.M = HDIM;
    p.s0.gx = HDIM / 128; p.s0.gy = NTOK / 128;
    p.s0.msplit = p.s0.gx; p.s0.epi = 0; p.s0.beta = 1;
    p.s1 = z;
    p.s1.Ah = Xh; p.s1.Al = Xl; p.s1.Bh = fuwh; p.s1.Bl = fuwl;
    p.s1.G = BG; p.s1.Oh = Ph; p.s1.Ol = Pl;
    p.s1.K = HDIM; p.s1.M = FDIM;
    p.s1.gx = FDIM / 128; p.s1.gy = NTOK / 128;
    p.s1.msplit = p.s1.gx; p.s1.epi = 2; p.s1.beta = 0;
    p.nb0 = (HDIM / 128) * (NTOK / 128);
    tc_gemm<<<p.nb0 + (FDIM / 128) * (NTOK / 128), 256, SMEM_TOTAL>>>(p);

    // Launch D — GEMM9: out += P @ fdw^T
    p = GPair{};
    p.s0 = z;
    p.s0.Ah = Ph; p.s0.Al = Pl; p.s0.Bh = fdwh; p.s0.Bl = fdwl;
    p.s0.C = out; p.s0.K = FDIM; p.s0.M = HDIM;
    p.s0.gx = HDIM / 128; p.s0.gy = NTOK / 128;
    p.s0.msplit = p.s0.gx; p.s0.epi = 0; p.s0.beta = 1;
    p.s1 = p.s0;
    p.nb0 = (HDIM / 128) * (NTOK / 128);
    tc_gemm<<<p.nb0, 256, SMEM_TOTAL>>>(p);
}